// round 15
// baseline (speedup 1.0000x reference)
#include <cuda_runtime.h>

// ---------------- problem constants ----------------
#define B_    2
#define NKEY  16384
#define DIM_  128
#define NQ    4096        // learned queries per batch
#define EOUT  256         // 2*DIM
#define TQ    128         // query tile per CTA (8 rows per thread)
#define TN    64          // key tile per iteration
#define HKEY  (NKEY/2)    // keys per split-K half
#define KPAD  132         // K/V smem row pitch (floats)
#define QPAD  132         // P^T smem row pitch (floats)
#define WPAD  129         // W smem row pitch

// scratch (allocation-free: __device__ globals)
__device__ float g_xn[(size_t)B_ * NKEY * DIM_];       // 16 MB: LayerNorm output
__device__ float g_po[2 * (size_t)B_ * NQ * DIM_];     // 16 MB: partial attn out (2 halves)
__device__ float g_ml[2 * (size_t)B_ * NQ * 2];        // (m, l) per half per row

// ---------------- packed f32x2 helpers ----------------
union F4U { float4 f; unsigned long long u[2]; };
union U2F { unsigned long long u; float2 f; };

__device__ __forceinline__ unsigned long long ffma2_(unsigned long long a,
                                                     unsigned long long b,
                                                     unsigned long long c) {
    unsigned long long d;
    asm("fma.rn.f32x2 %0, %1, %2, %3;" : "=l"(d) : "l"(a), "l"(b), "l"(c));
    return d;
}
__device__ __forceinline__ unsigned long long mul2_(unsigned long long a,
                                                    unsigned long long b) {
    unsigned long long d;
    asm("mul.rn.f32x2 %0, %1, %2;" : "=l"(d) : "l"(a), "l"(b));
    return d;
}
__device__ __forceinline__ unsigned long long pack2_(float x) {
    unsigned long long d;
    asm("mov.b64 %0, {%1, %1};" : "=l"(d) : "f"(x));
    return d;
}
__device__ __forceinline__ float ex2_(float x) {
    float y;
    asm("ex2.approx.f32 %0, %1;" : "=f"(y) : "f"(x));
    return y;
}

// ---------------- kernel 1: LayerNorm (warp per row) ----------------
__global__ __launch_bounds__(256) void ln_kernel(const float* __restrict__ x,
                                                 const float* __restrict__ gamma,
                                                 const float* __restrict__ beta) {
    int gwarp = (blockIdx.x * blockDim.x + threadIdx.x) >> 5;
    int lane  = threadIdx.x & 31;
    if (gwarp >= B_ * NKEY) return;

    float4 v = ((const float4*)x)[(size_t)gwarp * 32 + lane];
    float s  = v.x + v.y + v.z + v.w;
    float ss = v.x * v.x + v.y * v.y + v.z * v.z + v.w * v.w;
    #pragma unroll
    for (int o = 16; o; o >>= 1) {
        s  += __shfl_xor_sync(0xffffffffu, s,  o);
        ss += __shfl_xor_sync(0xffffffffu, ss, o);
    }
    float mu  = s  * (1.0f / DIM_);
    float var = ss * (1.0f / DIM_) - mu * mu;
    float r   = rsqrtf(var + 1e-5f);

    float4 g  = ((const float4*)gamma)[lane];
    float4 bb = ((const float4*)beta)[lane];
    float4 o4;
    o4.x = (v.x - mu) * r * g.x + bb.x;
    o4.y = (v.y - mu) * r * g.y + bb.y;
    o4.z = (v.z - mu) * r * g.z + bb.z;
    o4.w = (v.w - mu) * r * g.w + bb.w;
    ((float4*)g_xn)[(size_t)gwarp * 32 + lane] = o4;
}

// ---------------- kernel 2: flash cross-attention, split-K ----------------
// Grid: (NQ/TQ=32, B_=2, 2 key-halves) = 128 CTAs (one wave).
// Block: 256 threads. tx=tid&15 (4 k-cols: k=tx+16j), ty=tid>>4 (8 q-rows).
// Micro-tiles: QK 8q x 4k (packed over d), PV 8q x 8d (d in {4tx..+3, 64+4tx..+3}).
// Outputs UNNORMALIZED partial O plus (m, l) per row; merge deferred to linear.
__global__ __launch_bounds__(256) void attn_kernel(const float* __restrict__ queries) {
    extern __shared__ float smem[];
    float* Qs = smem;                       // [128][128]   64 KB
    float* Kv = Qs + TQ * DIM_;             // [64][KPAD]   33 KB
    float* Ps = Kv + TN * KPAD;             // [64][QPAD]   33 KB (P transposed: [k][q])

    const int tid = threadIdx.x;
    const int tx  = tid & 15;
    const int ty  = tid >> 4;
    const int b     = blockIdx.y;
    const int z     = blockIdx.z;
    const int qbase = blockIdx.x * TQ;
    const float qsc = 0.08838834764831845f * 1.4426950408889634f; // scale * log2(e)

    // load + scale Q tile (once)
    {
        const float4* qg = (const float4*)(queries + (size_t)qbase * DIM_);
        for (int i = tid; i < TQ * DIM_ / 4; i += 256) {
            float4 v = qg[i];
            v.x *= qsc; v.y *= qsc; v.z *= qsc; v.w *= qsc;
            ((float4*)Qs)[i] = v;
        }
    }

    unsigned long long o2[8][4];   // 8 q-rows x 4 d-pairs
    float m[8], l[8];
    #pragma unroll
    for (int i = 0; i < 8; i++) {
        m[i] = -1e30f; l[i] = 0.0f;
        #pragma unroll
        for (int d = 0; d < 4; d++) o2[i][d] = 0ull;
    }

    const float4* xb4   = (const float4*)(g_xn + ((size_t)b * NKEY + (size_t)z * HKEY) * DIM_);
    const float*  qrow0 = Qs + (8 * ty) * DIM_;
    const float*  krow0 = Kv + tx * KPAD;
    const float*  vca   = Kv + 4 * tx;        // d cols 4tx..4tx+3
    const float*  vcb   = Kv + 64 + 4 * tx;   // d cols 64+4tx..+3

    for (int kb = 0; kb < HKEY; kb += TN) {
        __syncthreads();                      // prev PV done reading Kv/Ps
        for (int i = tid; i < TN * DIM_ / 4; i += 256) {
            float4 v = xb4[(size_t)kb * (DIM_ / 4) + i];
            int row = i >> 5;
            int col = (i & 31) << 2;
            *(float4*)&Kv[row * KPAD + col] = v;
        }
        __syncthreads();

        // ---- S = Q*K^T (packed over d) ----
        unsigned long long s2[8][4];
        #pragma unroll
        for (int i = 0; i < 8; i++)
            #pragma unroll
            for (int j = 0; j < 4; j++) s2[i][j] = 0ull;

        #pragma unroll 4
        for (int d4 = 0; d4 < DIM_; d4 += 4) {
            unsigned long long k0[4], k1[4];
            #pragma unroll
            for (int j = 0; j < 4; j++) {
                F4U kk; kk.f = *(const float4*)&krow0[j * 16 * KPAD + d4];
                k0[j] = kk.u[0]; k1[j] = kk.u[1];
            }
            #pragma unroll
            for (int i = 0; i < 8; i++) {
                F4U qq; qq.f = *(const float4*)&qrow0[i * DIM_ + d4];
                #pragma unroll
                for (int j = 0; j < 4; j++) {
                    s2[i][j] = ffma2_(qq.u[0], k0[j], s2[i][j]);
                    s2[i][j] = ffma2_(qq.u[1], k1[j], s2[i][j]);
                }
            }
        }

        // ---- online softmax (exp2 domain); P stored transposed [k][q] ----
        #pragma unroll
        for (int i = 0; i < 8; i++) {
            float s[4];
            #pragma unroll
            for (int j = 0; j < 4; j++) {
                U2F t; t.u = s2[i][j];
                s[j] = t.f.x + t.f.y;
            }
            float mt = fmaxf(fmaxf(s[0], s[1]), fmaxf(s[2], s[3]));
            #pragma unroll
            for (int o = 8; o; o >>= 1)
                mt = fmaxf(mt, __shfl_xor_sync(0xffffffffu, mt, o));
            float mn    = fmaxf(m[i], mt);
            float alpha = ex2_(m[i] - mn);
            m[i] = mn;
            float rs = 0.0f;
            #pragma unroll
            for (int j = 0; j < 4; j++) {
                float p = ex2_(s[j] - mn);
                Ps[(tx + 16 * j) * QPAD + 8 * ty + i] = p;
                rs += p;
            }
            #pragma unroll
            for (int o = 8; o; o >>= 1)
                rs += __shfl_xor_sync(0xffffffffu, rs, o);
            l[i] = l[i] * alpha + rs;
            unsigned long long aa = pack2_(alpha);
            #pragma unroll
            for (int d = 0; d < 4; d++) o2[i][d] = mul2_(o2[i][d], aa);
        }
        __syncthreads();

        // ---- O += P * V (P via broadcast LDS.128, packed over d) ----
        #pragma unroll 2
        for (int k = 0; k < TN; k++) {
            F4U va, vb;
            va.f = *(const float4*)&vca[k * KPAD];
            vb.f = *(const float4*)&vcb[k * KPAD];
            float4 pA = *(const float4*)&Ps[k * QPAD + 8 * ty];
            float4 pB = *(const float4*)&Ps[k * QPAD + 8 * ty + 4];
            float pv[8] = {pA.x, pA.y, pA.z, pA.w, pB.x, pB.y, pB.z, pB.w};
            #pragma unroll
            for (int i = 0; i < 8; i++) {
                unsigned long long pp = pack2_(pv[i]);
                o2[i][0] = ffma2_(pp, va.u[0], o2[i][0]);
                o2[i][1] = ffma2_(pp, va.u[1], o2[i][1]);
                o2[i][2] = ffma2_(pp, vb.u[0], o2[i][2]);
                o2[i][3] = ffma2_(pp, vb.u[1], o2[i][3]);
            }
        }
    }

    // epilogue: write unnormalized partial O and (m, l)
    const size_t rowbase = (size_t)b * NQ + qbase + 8 * ty;
    #pragma unroll
    for (int i = 0; i < 8; i++) {
        U2F a0, a1, a2, a3;
        a0.u = o2[i][0]; a1.u = o2[i][1]; a2.u = o2[i][2]; a3.u = o2[i][3];
        float* orow = g_po + ((size_t)z * (B_ * NQ) + rowbase + i) * DIM_;
        *(float4*)(orow + 4 * tx)      = make_float4(a0.f.x, a0.f.y, a1.f.x, a1.f.y);
        *(float4*)(orow + 64 + 4 * tx) = make_float4(a2.f.x, a2.f.y, a3.f.x, a3.f.y);
        if (tx == 0) {
            float2 ml = make_float2(m[i], l[i]);
            *(float2*)&g_ml[((size_t)z * (B_ * NQ) + rowbase + i) * 2] = ml;
        }
    }
}

// ---------------- kernel 3: split-K merge + trailing linear (128 -> 256) ----------------
__global__ __launch_bounds__(256) void linear_kernel(const float* __restrict__ W,
                                                     float* __restrict__ out) {
    extern __shared__ float smem[];
    float* Ws = smem;                 // [256][WPAD]
    float* os = smem + EOUT * WPAD;   // [4][128]
    const int tid = threadIdx.x;
    const int r0  = blockIdx.x * 64;

    for (int i = tid; i < EOUT * DIM_; i += 256) {
        int e = i >> 7, d = i & 127;
        Ws[e * WPAD + d] = W[i];
    }
    const float* wrow = Ws + tid * WPAD;

    for (int rb = 0; rb < 64; rb += 4) {
        __syncthreads();
        // merge the two split-K partials while staging rows into smem
        for (int i = tid; i < 4 * DIM_; i += 256) {
            int rr = r0 + rb + (i >> 7);
            int d  = i & 127;
            float2 ml0 = *(const float2*)&g_ml[(size_t)rr * 2];
            float2 ml1 = *(const float2*)&g_ml[((size_t)(B_ * NQ) + rr) * 2];
            float mm = fmaxf(ml0.x, ml1.x);
            float c0 = ex2_(ml0.x - mm);
            float c1 = ex2_(ml1.x - mm);
            float invL = 1.0f / (ml0.y * c0 + ml1.y * c1);
            float v0 = g_po[(size_t)rr * DIM_ + d];
            float v1 = g_po[(size_t)(B_ * NQ) * DIM_ + (size_t)rr * DIM_ + d];
            os[i] = (v0 * c0 + v1 * c1) * invL;
        }
        __syncthreads();

        float acc0 = 0.f, acc1 = 0.f, acc2 = 0.f, acc3 = 0.f;
        #pragma unroll 8
        for (int d = 0; d < DIM_; d++) {
            float w = wrow[d];
            acc0 += w * os[d];
            acc1 += w * os[DIM_ + d];
            acc2 += w * os[2 * DIM_ + d];
            acc3 += w * os[3 * DIM_ + d];
        }
        size_t ob = (size_t)(r0 + rb) * EOUT + tid;
        out[ob]            = acc0;
        out[ob + EOUT]     = acc1;
        out[ob + 2 * EOUT] = acc2;
        out[ob + 3 * EOUT] = acc3;
    }
}

// ---------------- launch ----------------
extern "C" void kernel_launch(void* const* d_in, const int* in_sizes, int n_in,
                              void* d_out, int out_size) {
    const float* x       = (const float*)d_in[0];   // [2,16384,128]
    const float* gamma   = (const float*)d_in[1];   // [128]
    const float* beta    = (const float*)d_in[2];   // [128]
    const float* queries = (const float*)d_in[3];   // [4096,128]
    const float* W       = (const float*)d_in[4];   // [256,128]
    float* out = (float*)d_out;                     // [2,4096,256]

    const int attn_smem = (TQ * DIM_ + TN * KPAD + TN * QPAD) * (int)sizeof(float); // 133120
    const int lin_smem  = (EOUT * WPAD + 4 * DIM_) * (int)sizeof(float);            // 134144
    cudaFuncSetAttribute(attn_kernel,   cudaFuncAttributeMaxDynamicSharedMemorySize, attn_smem);
    cudaFuncSetAttribute(linear_kernel, cudaFuncAttributeMaxDynamicSharedMemorySize, lin_smem);

    ln_kernel<<<(B_ * NKEY) / 8, 256>>>(x, gamma, beta);
    attn_kernel<<<dim3(NQ / TQ, B_, 2), 256, attn_smem>>>(queries);  // 128 CTAs = 1 wave
    linear_kernel<<<(B_ * NQ) / 64, 256, lin_smem>>>(W, out);
}

// round 16
// speedup vs baseline: 1.0020x; 1.0020x over previous
#include <cuda_runtime.h>

// ---------------- problem constants ----------------
#define B_    2
#define NKEY  16384
#define DIM_  128
#define NQ    4096        // learned queries per batch
#define EOUT  256         // 2*DIM
#define TQ    128         // query tile per CTA (8 rows per thread)
#define TN    64          // key tile per iteration
#define HKEY  (NKEY/2)    // keys per split-K half
#define KPAD  132         // K/V smem row pitch (floats)
#define QPAD  132         // P^T smem row pitch (floats)
#define WPAD  129         // W smem row pitch

// scratch (allocation-free: __device__ globals)
__device__ float g_xn[(size_t)B_ * NKEY * DIM_];       // 16 MB: LayerNorm output
__device__ float g_po[2 * (size_t)B_ * NQ * DIM_];     // 16 MB: partial attn out (2 halves)
__device__ float g_ml[2 * (size_t)B_ * NQ * 2];        // (m, l) per half per row

// ---------------- packed f32x2 helpers ----------------
union F4U { float4 f; unsigned long long u[2]; };
union U2F { unsigned long long u; float2 f; };

__device__ __forceinline__ unsigned long long ffma2_(unsigned long long a,
                                                     unsigned long long b,
                                                     unsigned long long c) {
    unsigned long long d;
    asm("fma.rn.f32x2 %0, %1, %2, %3;" : "=l"(d) : "l"(a), "l"(b), "l"(c));
    return d;
}
__device__ __forceinline__ unsigned long long mul2_(unsigned long long a,
                                                    unsigned long long b) {
    unsigned long long d;
    asm("mul.rn.f32x2 %0, %1, %2;" : "=l"(d) : "l"(a), "l"(b));
    return d;
}
__device__ __forceinline__ unsigned long long pack2_(float x) {
    unsigned long long d;
    asm("mov.b64 %0, {%1, %1};" : "=l"(d) : "f"(x));
    return d;
}
__device__ __forceinline__ float ex2_(float x) {
    float y;
    asm("ex2.approx.f32 %0, %1;" : "=f"(y) : "f"(x));
    return y;
}

// ---------------- kernel 1: LayerNorm (warp per row) ----------------
__global__ __launch_bounds__(256) void ln_kernel(const float* __restrict__ x,
                                                 const float* __restrict__ gamma,
                                                 const float* __restrict__ beta) {
    int gwarp = (blockIdx.x * blockDim.x + threadIdx.x) >> 5;
    int lane  = threadIdx.x & 31;
    if (gwarp >= B_ * NKEY) return;

    float4 v = ((const float4*)x)[(size_t)gwarp * 32 + lane];
    float s  = v.x + v.y + v.z + v.w;
    float ss = v.x * v.x + v.y * v.y + v.z * v.z + v.w * v.w;
    #pragma unroll
    for (int o = 16; o; o >>= 1) {
        s  += __shfl_xor_sync(0xffffffffu, s,  o);
        ss += __shfl_xor_sync(0xffffffffu, ss, o);
    }
    float mu  = s  * (1.0f / DIM_);
    float var = ss * (1.0f / DIM_) - mu * mu;
    float r   = rsqrtf(var + 1e-5f);

    float4 g  = ((const float4*)gamma)[lane];
    float4 bb = ((const float4*)beta)[lane];
    float4 o4;
    o4.x = (v.x - mu) * r * g.x + bb.x;
    o4.y = (v.y - mu) * r * g.y + bb.y;
    o4.z = (v.z - mu) * r * g.z + bb.z;
    o4.w = (v.w - mu) * r * g.w + bb.w;
    ((float4*)g_xn)[(size_t)gwarp * 32 + lane] = o4;
}

// ---------------- kernel 2: flash cross-attention, split-K ----------------
// Grid: (NQ/TQ=32, B_=2, 2 key-halves) = 128 CTAs (one wave).
// Block: 256 threads. tx=tid&15 (4 k-cols: k=tx+16j), ty=tid>>4 (8 q-rows).
// Micro-tiles: QK 8q x 4k (packed over d), PV 8q x 8d (d in {4tx..+3, 64+4tx..+3}).
// Outputs UNNORMALIZED partial O plus (m, l) per row; merge deferred to linear.
__global__ __launch_bounds__(256) void attn_kernel(const float* __restrict__ queries) {
    extern __shared__ float smem[];
    float* Qs = smem;                       // [128][128]   64 KB
    float* Kv = Qs + TQ * DIM_;             // [64][KPAD]   33 KB
    float* Ps = Kv + TN * KPAD;             // [64][QPAD]   33 KB (P transposed: [k][q])

    const int tid = threadIdx.x;
    const int tx  = tid & 15;
    const int ty  = tid >> 4;
    const int b     = blockIdx.y;
    const int z     = blockIdx.z;
    const int qbase = blockIdx.x * TQ;
    const float qsc = 0.08838834764831845f * 1.4426950408889634f; // scale * log2(e)

    // load + scale Q tile (once)
    {
        const float4* qg = (const float4*)(queries + (size_t)qbase * DIM_);
        for (int i = tid; i < TQ * DIM_ / 4; i += 256) {
            float4 v = qg[i];
            v.x *= qsc; v.y *= qsc; v.z *= qsc; v.w *= qsc;
            ((float4*)Qs)[i] = v;
        }
    }

    unsigned long long o2[8][4];   // 8 q-rows x 4 d-pairs
    float m[8], l[8];
    #pragma unroll
    for (int i = 0; i < 8; i++) {
        m[i] = -1e30f; l[i] = 0.0f;
        #pragma unroll
        for (int d = 0; d < 4; d++) o2[i][d] = 0ull;
    }

    const float4* xb4   = (const float4*)(g_xn + ((size_t)b * NKEY + (size_t)z * HKEY) * DIM_);
    const float*  qrow0 = Qs + (8 * ty) * DIM_;
    const float*  krow0 = Kv + tx * KPAD;
    const float*  vca   = Kv + 4 * tx;        // d cols 4tx..4tx+3
    const float*  vcb   = Kv + 64 + 4 * tx;   // d cols 64+4tx..+3

    for (int kb = 0; kb < HKEY; kb += TN) {
        __syncthreads();                      // prev PV done reading Kv/Ps
        for (int i = tid; i < TN * DIM_ / 4; i += 256) {
            float4 v = xb4[(size_t)kb * (DIM_ / 4) + i];
            int row = i >> 5;
            int col = (i & 31) << 2;
            *(float4*)&Kv[row * KPAD + col] = v;
        }
        __syncthreads();

        // ---- S = Q*K^T (packed over d) ----
        unsigned long long s2[8][4];
        #pragma unroll
        for (int i = 0; i < 8; i++)
            #pragma unroll
            for (int j = 0; j < 4; j++) s2[i][j] = 0ull;

        #pragma unroll 4
        for (int d4 = 0; d4 < DIM_; d4 += 4) {
            unsigned long long k0[4], k1[4];
            #pragma unroll
            for (int j = 0; j < 4; j++) {
                F4U kk; kk.f = *(const float4*)&krow0[j * 16 * KPAD + d4];
                k0[j] = kk.u[0]; k1[j] = kk.u[1];
            }
            #pragma unroll
            for (int i = 0; i < 8; i++) {
                F4U qq; qq.f = *(const float4*)&qrow0[i * DIM_ + d4];
                #pragma unroll
                for (int j = 0; j < 4; j++) {
                    s2[i][j] = ffma2_(qq.u[0], k0[j], s2[i][j]);
                    s2[i][j] = ffma2_(qq.u[1], k1[j], s2[i][j]);
                }
            }
        }

        // ---- online softmax (exp2 domain); P stored transposed [k][q] ----
        #pragma unroll
        for (int i = 0; i < 8; i++) {
            float s[4];
            #pragma unroll
            for (int j = 0; j < 4; j++) {
                U2F t; t.u = s2[i][j];
                s[j] = t.f.x + t.f.y;
            }
            float mt = fmaxf(fmaxf(s[0], s[1]), fmaxf(s[2], s[3]));
            #pragma unroll
            for (int o = 8; o; o >>= 1)
                mt = fmaxf(mt, __shfl_xor_sync(0xffffffffu, mt, o));
            float mn    = fmaxf(m[i], mt);
            float alpha = ex2_(m[i] - mn);
            m[i] = mn;
            float rs = 0.0f;
            #pragma unroll
            for (int j = 0; j < 4; j++) {
                float p = ex2_(s[j] - mn);
                Ps[(tx + 16 * j) * QPAD + 8 * ty + i] = p;
                rs += p;
            }
            #pragma unroll
            for (int o = 8; o; o >>= 1)
                rs += __shfl_xor_sync(0xffffffffu, rs, o);
            l[i] = l[i] * alpha + rs;
            unsigned long long aa = pack2_(alpha);
            #pragma unroll
            for (int d = 0; d < 4; d++) o2[i][d] = mul2_(o2[i][d], aa);
        }
        __syncthreads();

        // ---- O += P * V (P via broadcast LDS.128, packed over d) ----
        #pragma unroll 2
        for (int k = 0; k < TN; k++) {
            F4U va, vb;
            va.f = *(const float4*)&vca[k * KPAD];
            vb.f = *(const float4*)&vcb[k * KPAD];
            float4 pA = *(const float4*)&Ps[k * QPAD + 8 * ty];
            float4 pB = *(const float4*)&Ps[k * QPAD + 8 * ty + 4];
            float pv[8] = {pA.x, pA.y, pA.z, pA.w, pB.x, pB.y, pB.z, pB.w};
            #pragma unroll
            for (int i = 0; i < 8; i++) {
                unsigned long long pp = pack2_(pv[i]);
                o2[i][0] = ffma2_(pp, va.u[0], o2[i][0]);
                o2[i][1] = ffma2_(pp, va.u[1], o2[i][1]);
                o2[i][2] = ffma2_(pp, vb.u[0], o2[i][2]);
                o2[i][3] = ffma2_(pp, vb.u[1], o2[i][3]);
            }
        }
    }

    // epilogue: write unnormalized partial O and (m, l)
    const size_t rowbase = (size_t)b * NQ + qbase + 8 * ty;
    #pragma unroll
    for (int i = 0; i < 8; i++) {
        U2F a0, a1, a2, a3;
        a0.u = o2[i][0]; a1.u = o2[i][1]; a2.u = o2[i][2]; a3.u = o2[i][3];
        float* orow = g_po + ((size_t)z * (B_ * NQ) + rowbase + i) * DIM_;
        *(float4*)(orow + 4 * tx)      = make_float4(a0.f.x, a0.f.y, a1.f.x, a1.f.y);
        *(float4*)(orow + 64 + 4 * tx) = make_float4(a2.f.x, a2.f.y, a3.f.x, a3.f.y);
        if (tx == 0) {
            float2 ml = make_float2(m[i], l[i]);
            *(float2*)&g_ml[((size_t)z * (B_ * NQ) + rowbase + i) * 2] = ml;
        }
    }
}

// ---------------- kernel 3: split-K merge + trailing linear (128 -> 256) ----------------
__global__ __launch_bounds__(256) void linear_kernel(const float* __restrict__ W,
                                                     float* __restrict__ out) {
    extern __shared__ float smem[];
    float* Ws = smem;                 // [256][WPAD]
    float* os = smem + EOUT * WPAD;   // [4][128]
    const int tid = threadIdx.x;
    const int r0  = blockIdx.x * 64;

    for (int i = tid; i < EOUT * DIM_; i += 256) {
        int e = i >> 7, d = i & 127;
        Ws[e * WPAD + d] = W[i];
    }
    const float* wrow = Ws + tid * WPAD;

    for (int rb = 0; rb < 64; rb += 4) {
        __syncthreads();
        // merge the two split-K partials while staging rows into smem
        for (int i = tid; i < 4 * DIM_; i += 256) {
            int rr = r0 + rb + (i >> 7);
            int d  = i & 127;
            float2 ml0 = *(const float2*)&g_ml[(size_t)rr * 2];
            float2 ml1 = *(const float2*)&g_ml[((size_t)(B_ * NQ) + rr) * 2];
            float mm = fmaxf(ml0.x, ml1.x);
            float c0 = ex2_(ml0.x - mm);
            float c1 = ex2_(ml1.x - mm);
            float invL = 1.0f / (ml0.y * c0 + ml1.y * c1);
            float v0 = g_po[(size_t)rr * DIM_ + d];
            float v1 = g_po[(size_t)(B_ * NQ) * DIM_ + (size_t)rr * DIM_ + d];
            os[i] = (v0 * c0 + v1 * c1) * invL;
        }
        __syncthreads();

        float acc0 = 0.f, acc1 = 0.f, acc2 = 0.f, acc3 = 0.f;
        #pragma unroll 8
        for (int d = 0; d < DIM_; d++) {
            float w = wrow[d];
            acc0 += w * os[d];
            acc1 += w * os[DIM_ + d];
            acc2 += w * os[2 * DIM_ + d];
            acc3 += w * os[3 * DIM_ + d];
        }
        size_t ob = (size_t)(r0 + rb) * EOUT + tid;
        out[ob]            = acc0;
        out[ob + EOUT]     = acc1;
        out[ob + 2 * EOUT] = acc2;
        out[ob + 3 * EOUT] = acc3;
    }
}

// ---------------- launch ----------------
extern "C" void kernel_launch(void* const* d_in, const int* in_sizes, int n_in,
                              void* d_out, int out_size) {
    const float* x       = (const float*)d_in[0];   // [2,16384,128]
    const float* gamma   = (const float*)d_in[1];   // [128]
    const float* beta    = (const float*)d_in[2];   // [128]
    const float* queries = (const float*)d_in[3];   // [4096,128]
    const float* W       = (const float*)d_in[4];   // [256,128]
    float* out = (float*)d_out;                     // [2,4096,256]

    const int attn_smem = (TQ * DIM_ + TN * KPAD + TN * QPAD) * (int)sizeof(float); // 133120
    const int lin_smem  = (EOUT * WPAD + 4 * DIM_) * (int)sizeof(float);            // 134144
    cudaFuncSetAttribute(attn_kernel,   cudaFuncAttributeMaxDynamicSharedMemorySize, attn_smem);
    cudaFuncSetAttribute(linear_kernel, cudaFuncAttributeMaxDynamicSharedMemorySize, lin_smem);

    ln_kernel<<<(B_ * NKEY) / 8, 256>>>(x, gamma, beta);
    attn_kernel<<<dim3(NQ / TQ, B_, 2), 256, attn_smem>>>(queries);  // 128 CTAs = 1 wave
    linear_kernel<<<(B_ * NQ) / 64, 256, lin_smem>>>(W, out);
}

// round 17
// speedup vs baseline: 1.0028x; 1.0009x over previous
#include <cuda_runtime.h>

// ---------------- problem constants ----------------
#define B_    2
#define NKEY  16384
#define DIM_  128
#define NQ    4096        // learned queries per batch
#define EOUT  256         // 2*DIM
#define TQ    128         // query tile per CTA (8 rows per thread)
#define TN    64          // key tile per iteration
#define HKEY  (NKEY/2)    // keys per split-K half
#define KPAD  132         // K/V smem row pitch (floats)
#define QPAD  132         // P^T smem row pitch (floats)
#define WPAD  129         // W smem row pitch

// scratch (allocation-free: __device__ globals)
__device__ float g_xn[(size_t)B_ * NKEY * DIM_];       // 16 MB: LayerNorm output
__device__ float g_po[2 * (size_t)B_ * NQ * DIM_];     // 16 MB: partial attn out (2 halves)
__device__ float g_ml[2 * (size_t)B_ * NQ * 2];        // (m, l) per half per row

// ---------------- packed f32x2 helpers ----------------
union F4U { float4 f; unsigned long long u[2]; };
union U2F { unsigned long long u; float2 f; };

__device__ __forceinline__ unsigned long long ffma2_(unsigned long long a,
                                                     unsigned long long b,
                                                     unsigned long long c) {
    unsigned long long d;
    asm("fma.rn.f32x2 %0, %1, %2, %3;" : "=l"(d) : "l"(a), "l"(b), "l"(c));
    return d;
}
__device__ __forceinline__ unsigned long long mul2_(unsigned long long a,
                                                    unsigned long long b) {
    unsigned long long d;
    asm("mul.rn.f32x2 %0, %1, %2;" : "=l"(d) : "l"(a), "l"(b));
    return d;
}
__device__ __forceinline__ unsigned long long pack2_(float x) {
    unsigned long long d;
    asm("mov.b64 %0, {%1, %1};" : "=l"(d) : "f"(x));
    return d;
}
__device__ __forceinline__ float ex2_(float x) {
    float y;
    asm("ex2.approx.f32 %0, %1;" : "=f"(y) : "f"(x));
    return y;
}

// ---------------- kernel 1: LayerNorm (warp per row) ----------------
__global__ __launch_bounds__(256) void ln_kernel(const float* __restrict__ x,
                                                 const float* __restrict__ gamma,
                                                 const float* __restrict__ beta) {
    int gwarp = (blockIdx.x * blockDim.x + threadIdx.x) >> 5;
    int lane  = threadIdx.x & 31;
    if (gwarp >= B_ * NKEY) return;

    float4 v = ((const float4*)x)[(size_t)gwarp * 32 + lane];
    float s  = v.x + v.y + v.z + v.w;
    float ss = v.x * v.x + v.y * v.y + v.z * v.z + v.w * v.w;
    #pragma unroll
    for (int o = 16; o; o >>= 1) {
        s  += __shfl_xor_sync(0xffffffffu, s,  o);
        ss += __shfl_xor_sync(0xffffffffu, ss, o);
    }
    float mu  = s  * (1.0f / DIM_);
    float var = ss * (1.0f / DIM_) - mu * mu;
    float r   = rsqrtf(var + 1e-5f);

    float4 g  = ((const float4*)gamma)[lane];
    float4 bb = ((const float4*)beta)[lane];
    float4 o4;
    o4.x = (v.x - mu) * r * g.x + bb.x;
    o4.y = (v.y - mu) * r * g.y + bb.y;
    o4.z = (v.z - mu) * r * g.z + bb.z;
    o4.w = (v.w - mu) * r * g.w + bb.w;
    ((float4*)g_xn)[(size_t)gwarp * 32 + lane] = o4;
}

// ---------------- kernel 2: flash cross-attention, split-K ----------------
// Grid: (NQ/TQ=32, B_=2, 2 key-halves) = 128 CTAs (one wave).
// Block: 256 threads. tx=tid&15 (4 k-cols: k=tx+16j), ty=tid>>4 (8 q-rows).
// Micro-tiles: QK 8q x 4k (packed over d), PV 8q x 8d (d in {4tx..+3, 64+4tx..+3}).
// Outputs UNNORMALIZED partial O plus (m, l) per row; merge deferred to linear.
__global__ __launch_bounds__(256) void attn_kernel(const float* __restrict__ queries) {
    extern __shared__ float smem[];
    float* Qs = smem;                       // [128][128]   64 KB
    float* Kv = Qs + TQ * DIM_;             // [64][KPAD]   33 KB
    float* Ps = Kv + TN * KPAD;             // [64][QPAD]   33 KB (P transposed: [k][q])

    const int tid = threadIdx.x;
    const int tx  = tid & 15;
    const int ty  = tid >> 4;
    const int b     = blockIdx.y;
    const int z     = blockIdx.z;
    const int qbase = blockIdx.x * TQ;
    const float qsc = 0.08838834764831845f * 1.4426950408889634f; // scale * log2(e)

    // load + scale Q tile (once)
    {
        const float4* qg = (const float4*)(queries + (size_t)qbase * DIM_);
        for (int i = tid; i < TQ * DIM_ / 4; i += 256) {
            float4 v = qg[i];
            v.x *= qsc; v.y *= qsc; v.z *= qsc; v.w *= qsc;
            ((float4*)Qs)[i] = v;
        }
    }

    unsigned long long o2[8][4];   // 8 q-rows x 4 d-pairs
    float m[8], l[8];
    #pragma unroll
    for (int i = 0; i < 8; i++) {
        m[i] = -1e30f; l[i] = 0.0f;
        #pragma unroll
        for (int d = 0; d < 4; d++) o2[i][d] = 0ull;
    }

    const float4* xb4   = (const float4*)(g_xn + ((size_t)b * NKEY + (size_t)z * HKEY) * DIM_);
    const float*  qrow0 = Qs + (8 * ty) * DIM_;
    const float*  krow0 = Kv + tx * KPAD;
    const float*  vca   = Kv + 4 * tx;        // d cols 4tx..4tx+3
    const float*  vcb   = Kv + 64 + 4 * tx;   // d cols 64+4tx..+3

    for (int kb = 0; kb < HKEY; kb += TN) {
        __syncthreads();                      // prev PV done reading Kv/Ps
        for (int i = tid; i < TN * DIM_ / 4; i += 256) {
            float4 v = xb4[(size_t)kb * (DIM_ / 4) + i];
            int row = i >> 5;
            int col = (i & 31) << 2;
            *(float4*)&Kv[row * KPAD + col] = v;
        }
        __syncthreads();

        // ---- S = Q*K^T (packed over d) ----
        unsigned long long s2[8][4];
        #pragma unroll
        for (int i = 0; i < 8; i++)
            #pragma unroll
            for (int j = 0; j < 4; j++) s2[i][j] = 0ull;

        #pragma unroll 4
        for (int d4 = 0; d4 < DIM_; d4 += 4) {
            unsigned long long k0[4], k1[4];
            #pragma unroll
            for (int j = 0; j < 4; j++) {
                F4U kk; kk.f = *(const float4*)&krow0[j * 16 * KPAD + d4];
                k0[j] = kk.u[0]; k1[j] = kk.u[1];
            }
            #pragma unroll
            for (int i = 0; i < 8; i++) {
                F4U qq; qq.f = *(const float4*)&qrow0[i * DIM_ + d4];
                #pragma unroll
                for (int j = 0; j < 4; j++) {
                    s2[i][j] = ffma2_(qq.u[0], k0[j], s2[i][j]);
                    s2[i][j] = ffma2_(qq.u[1], k1[j], s2[i][j]);
                }
            }
        }

        // ---- online softmax (exp2 domain); P stored transposed [k][q] ----
        #pragma unroll
        for (int i = 0; i < 8; i++) {
            float s[4];
            #pragma unroll
            for (int j = 0; j < 4; j++) {
                U2F t; t.u = s2[i][j];
                s[j] = t.f.x + t.f.y;
            }
            float mt = fmaxf(fmaxf(s[0], s[1]), fmaxf(s[2], s[3]));
            #pragma unroll
            for (int o = 8; o; o >>= 1)
                mt = fmaxf(mt, __shfl_xor_sync(0xffffffffu, mt, o));
            float mn    = fmaxf(m[i], mt);
            float alpha = ex2_(m[i] - mn);
            m[i] = mn;
            float rs = 0.0f;
            #pragma unroll
            for (int j = 0; j < 4; j++) {
                float p = ex2_(s[j] - mn);
                Ps[(tx + 16 * j) * QPAD + 8 * ty + i] = p;
                rs += p;
            }
            #pragma unroll
            for (int o = 8; o; o >>= 1)
                rs += __shfl_xor_sync(0xffffffffu, rs, o);
            l[i] = l[i] * alpha + rs;
            unsigned long long aa = pack2_(alpha);
            #pragma unroll
            for (int d = 0; d < 4; d++) o2[i][d] = mul2_(o2[i][d], aa);
        }
        __syncthreads();

        // ---- O += P * V (P via broadcast LDS.128, packed over d) ----
        #pragma unroll 2
        for (int k = 0; k < TN; k++) {
            F4U va, vb;
            va.f = *(const float4*)&vca[k * KPAD];
            vb.f = *(const float4*)&vcb[k * KPAD];
            float4 pA = *(const float4*)&Ps[k * QPAD + 8 * ty];
            float4 pB = *(const float4*)&Ps[k * QPAD + 8 * ty + 4];
            float pv[8] = {pA.x, pA.y, pA.z, pA.w, pB.x, pB.y, pB.z, pB.w};
            #pragma unroll
            for (int i = 0; i < 8; i++) {
                unsigned long long pp = pack2_(pv[i]);
                o2[i][0] = ffma2_(pp, va.u[0], o2[i][0]);
                o2[i][1] = ffma2_(pp, va.u[1], o2[i][1]);
                o2[i][2] = ffma2_(pp, vb.u[0], o2[i][2]);
                o2[i][3] = ffma2_(pp, vb.u[1], o2[i][3]);
            }
        }
    }

    // epilogue: write unnormalized partial O and (m, l)
    const size_t rowbase = (size_t)b * NQ + qbase + 8 * ty;
    #pragma unroll
    for (int i = 0; i < 8; i++) {
        U2F a0, a1, a2, a3;
        a0.u = o2[i][0]; a1.u = o2[i][1]; a2.u = o2[i][2]; a3.u = o2[i][3];
        float* orow = g_po + ((size_t)z * (B_ * NQ) + rowbase + i) * DIM_;
        *(float4*)(orow + 4 * tx)      = make_float4(a0.f.x, a0.f.y, a1.f.x, a1.f.y);
        *(float4*)(orow + 64 + 4 * tx) = make_float4(a2.f.x, a2.f.y, a3.f.x, a3.f.y);
        if (tx == 0) {
            float2 ml = make_float2(m[i], l[i]);
            *(float2*)&g_ml[((size_t)z * (B_ * NQ) + rowbase + i) * 2] = ml;
        }
    }
}

// ---------------- kernel 3: split-K merge + trailing linear (128 -> 256) ----------------
__global__ __launch_bounds__(256) void linear_kernel(const float* __restrict__ W,
                                                     float* __restrict__ out) {
    extern __shared__ float smem[];
    float* Ws = smem;                 // [256][WPAD]
    float* os = smem + EOUT * WPAD;   // [4][128]
    const int tid = threadIdx.x;
    const int r0  = blockIdx.x * 64;

    for (int i = tid; i < EOUT * DIM_; i += 256) {
        int e = i >> 7, d = i & 127;
        Ws[e * WPAD + d] = W[i];
    }
    const float* wrow = Ws + tid * WPAD;

    for (int rb = 0; rb < 64; rb += 4) {
        __syncthreads();
        // merge the two split-K partials while staging rows into smem
        for (int i = tid; i < 4 * DIM_; i += 256) {
            int rr = r0 + rb + (i >> 7);
            int d  = i & 127;
            float2 ml0 = *(const float2*)&g_ml[(size_t)rr * 2];
            float2 ml1 = *(const float2*)&g_ml[((size_t)(B_ * NQ) + rr) * 2];
            float mm = fmaxf(ml0.x, ml1.x);
            float c0 = ex2_(ml0.x - mm);
            float c1 = ex2_(ml1.x - mm);
            float invL = 1.0f / (ml0.y * c0 + ml1.y * c1);
            float v0 = g_po[(size_t)rr * DIM_ + d];
            float v1 = g_po[(size_t)(B_ * NQ) * DIM_ + (size_t)rr * DIM_ + d];
            os[i] = (v0 * c0 + v1 * c1) * invL;
        }
        __syncthreads();

        float acc0 = 0.f, acc1 = 0.f, acc2 = 0.f, acc3 = 0.f;
        #pragma unroll 8
        for (int d = 0; d < DIM_; d++) {
            float w = wrow[d];
            acc0 += w * os[d];
            acc1 += w * os[DIM_ + d];
            acc2 += w * os[2 * DIM_ + d];
            acc3 += w * os[3 * DIM_ + d];
        }
        size_t ob = (size_t)(r0 + rb) * EOUT + tid;
        out[ob]            = acc0;
        out[ob + EOUT]     = acc1;
        out[ob + 2 * EOUT] = acc2;
        out[ob + 3 * EOUT] = acc3;
    }
}

// ---------------- launch ----------------
extern "C" void kernel_launch(void* const* d_in, const int* in_sizes, int n_in,
                              void* d_out, int out_size) {
    const float* x       = (const float*)d_in[0];   // [2,16384,128]
    const float* gamma   = (const float*)d_in[1];   // [128]
    const float* beta    = (const float*)d_in[2];   // [128]
    const float* queries = (const float*)d_in[3];   // [4096,128]
    const float* W       = (const float*)d_in[4];   // [256,128]
    float* out = (float*)d_out;                     // [2,4096,256]

    const int attn_smem = (TQ * DIM_ + TN * KPAD + TN * QPAD) * (int)sizeof(float); // 133120
    const int lin_smem  = (EOUT * WPAD + 4 * DIM_) * (int)sizeof(float);            // 134144
    cudaFuncSetAttribute(attn_kernel,   cudaFuncAttributeMaxDynamicSharedMemorySize, attn_smem);
    cudaFuncSetAttribute(linear_kernel, cudaFuncAttributeMaxDynamicSharedMemorySize, lin_smem);

    ln_kernel<<<(B_ * NKEY) / 8, 256>>>(x, gamma, beta);
    attn_kernel<<<dim3(NQ / TQ, B_, 2), 256, attn_smem>>>(queries);  // 128 CTAs = 1 wave
    linear_kernel<<<(B_ * NQ) / 64, 256, lin_smem>>>(W, out);
}